// round 5
// baseline (speedup 1.0000x reference)
#include <cuda_runtime.h>

#define TT 512
#define BB 64
#define NN 1024
#define BN (BB * NN)

#define REST 0.0f
#define DECAY 0.2f
#define THRESHOLD 0.3f
#define BETA 0.02f

// 2 MB scratch for transposed temporal encoding: TEt[t][n] = TE[n][t]
__device__ float g_TEt[TT * NN];

// Tiled transpose: TE[N][T] (row-major) -> g_TEt[T][N]
__global__ void telif_transpose_te(const float* __restrict__ TE) {
    __shared__ float tile[32][33];
    const int tBase = blockIdx.x * 32;  // t tile origin
    const int nBase = blockIdx.y * 32;  // n tile origin
    const int lx = threadIdx.x;         // 0..31
    const int ly = threadIdx.y;         // 0..7

    // Coalesced read over t: tile[n_local][t_local]
#pragma unroll
    for (int i = 0; i < 32; i += 8) {
        tile[ly + i][lx] = TE[(size_t)(nBase + ly + i) * TT + (tBase + lx)];
    }
    __syncthreads();
    // Coalesced write over n
#pragma unroll
    for (int i = 0; i < 32; i += 8) {
        g_TEt[(size_t)(tBase + ly + i) * NN + (nBase + lx)] = tile[lx][ly + i];
    }
}

// One thread per neuron (b,n). Sequential over T with unroll-8 prefetch.
__global__ __launch_bounds__(128) void telif_kernel(const float* __restrict__ tx,
                                                    float* __restrict__ out) {
    const int idx = blockIdx.x * 128 + threadIdx.x;  // = b*N + n
    const int n = idx & (NN - 1);

    float v = REST;
    float y = 0.0f;
    float th = THRESHOLD;

    const float* xp = tx + idx;
    float* op = out + idx;
    const float* tep = g_TEt + n;

#pragma unroll 1
    for (int t = 0; t < TT; t += 8) {
        float xv[8], te[8];
        // Front-batched independent loads: MLP = 16, hides DRAM latency.
#pragma unroll
        for (int u = 0; u < 8; u++) {
            xv[u] = __ldcs(xp + (size_t)(t + u) * BN);   // streamed, evict-first
            te[u] = __ldg(tep + (size_t)(t + u) * NN);   // L2-resident (2 MB, reused x64)
        }
#pragma unroll
        for (int u = 0; u < 8; u++) {
            // Keep arithmetic in the reference's written order; nvcc default
            // FMA contraction mirrors XLA GPU's FPOpFusion::Fast.
            th = th + v * te[u] - (th - THRESHOLD) * BETA;
            v = v * DECAY * (1.0f - y) + xv[u];
            y = (v > th) ? 1.0f : 0.0f;
            __stcs(op + (size_t)(t + u) * BN, y);        // streamed store
        }
    }
}

extern "C" void kernel_launch(void* const* d_in, const int* in_sizes, int n_in,
                              void* d_out, int out_size) {
    const float* tx = (const float*)d_in[0];  // [T,B,N] = 33554432 f32
    const float* TE = (const float*)d_in[1];  // [N,T]   = 524288 f32
    float* out = (float*)d_out;               // [T,B,N] f32

    (void)in_sizes; (void)n_in; (void)out_size;

    dim3 tgrid(TT / 32, NN / 32);
    dim3 tblock(32, 8);
    telif_transpose_te<<<tgrid, tblock>>>(TE);

    telif_kernel<<<BN / 128, 128>>>(tx, out);
}

// round 7
// speedup vs baseline: 1.2609x; 1.2609x over previous
#include <cuda_runtime.h>

#define TT 512
#define BB 64
#define NN 1024
#define BN (BB * NN)

#define REST 0.0f
#define DECAY 0.2f
#define THRESHOLD 0.3f
#define BETA 0.02f

// 2 MB scratch for transposed temporal encoding: TEt[t][n] = TE[n][t]
__device__ float g_TEt[TT * NN];

// Tiled transpose: TE[N][T] (row-major) -> g_TEt[T][N]
__global__ void telif_transpose_te(const float* __restrict__ TE) {
    __shared__ float tile[32][33];
    const int tBase = blockIdx.x * 32;  // t tile origin
    const int nBase = blockIdx.y * 32;  // n tile origin
    const int lx = threadIdx.x;         // 0..31
    const int ly = threadIdx.y;         // 0..7

#pragma unroll
    for (int i = 0; i < 32; i += 8) {
        tile[ly + i][lx] = TE[(size_t)(nBase + ly + i) * TT + (tBase + lx)];
    }
    __syncthreads();
#pragma unroll
    for (int i = 0; i < 32; i += 8) {
        g_TEt[(size_t)(tBase + ly + i) * NN + (nBase + lx)] = tile[lx][ly + i];
    }
}

// One thread per neuron (b,n). 32-step super-iterations, double-buffered
// 16-step chunks: prefetch B while computing A, prefetch A while computing B.
__global__ __launch_bounds__(128) void telif_kernel(const float* __restrict__ tx,
                                                    float* __restrict__ out) {
    const int idx = blockIdx.x * 128 + threadIdx.x;  // = b*N + n
    const int n = idx & (NN - 1);

    float v = REST;
    float y = 0.0f;
    float th = THRESHOLD;

    const float* xp = tx + idx;
    float* op = out + idx;
    const float* tep = g_TEt + n;

    float xa[16], ta[16], xb[16], tb[16];

    // Prologue: fill buffer A with steps 0..15
#pragma unroll
    for (int u = 0; u < 16; u++) {
        xa[u] = __ldcs(xp + (size_t)u * BN);
        ta[u] = __ldg(tep + (size_t)u * NN);
    }

#pragma unroll 1
    for (int t = 0; t < TT; t += 32) {
        // Prefetch buffer B (steps t+16..t+31) before computing A
#pragma unroll
        for (int u = 0; u < 16; u++) {
            xb[u] = __ldcs(xp + (size_t)(t + 16 + u) * BN);
            tb[u] = __ldg(tep + (size_t)(t + 16 + u) * NN);
        }

        // Compute steps t..t+15 from A  (expressions identical to passing R2 kernel)
#pragma unroll
        for (int u = 0; u < 16; u++) {
            th = th + v * ta[u] - (th - THRESHOLD) * BETA;
            v = v * DECAY * (1.0f - y) + xa[u];
            y = (v > th) ? 1.0f : 0.0f;
            __stcs(op + (size_t)(t + u) * BN, y);
        }

        // Prefetch buffer A (steps t+32..t+47) before computing B
        if (t + 32 < TT) {
#pragma unroll
            for (int u = 0; u < 16; u++) {
                xa[u] = __ldcs(xp + (size_t)(t + 32 + u) * BN);
                ta[u] = __ldg(tep + (size_t)(t + 32 + u) * NN);
            }
        }

        // Compute steps t+16..t+31 from B
#pragma unroll
        for (int u = 0; u < 16; u++) {
            th = th + v * tb[u] - (th - THRESHOLD) * BETA;
            v = v * DECAY * (1.0f - y) + xb[u];
            y = (v > th) ? 1.0f : 0.0f;
            __stcs(op + (size_t)(t + 16 + u) * BN, y);
        }
    }
}

extern "C" void kernel_launch(void* const* d_in, const int* in_sizes, int n_in,
                              void* d_out, int out_size) {
    const float* tx = (const float*)d_in[0];  // [T,B,N] = 33554432 f32
    const float* TE = (const float*)d_in[1];  // [N,T]   = 524288 f32
    float* out = (float*)d_out;               // [T,B,N] f32

    (void)in_sizes; (void)n_in; (void)out_size;

    dim3 tgrid(TT / 32, NN / 32);
    dim3 tblock(32, 8);
    telif_transpose_te<<<tgrid, tblock>>>(TE);

    telif_kernel<<<BN / 128, 128>>>(tx, out);
}